// round 14
// baseline (speedup 1.0000x reference)
#include <cuda_runtime.h>

// SparseEmbedding: out[b, :] = sum_n vals[b,n] * kernel[idx[b,n], :] + bias
// BATCH=4096, NNZ=32, VOCAB=1e6, DIM=64. float32 everywhere, idx int32.
//
// R13 (final config = R8, measured best 8.32us): one warp per batch row,
// all 32 gathers front-batched into registers (MLP=32/warp) via __ldcg
// (L2-direct), 24 warps/SM (regs=80, 3 CTAs/SM) -> ~768 lines in flight/SM,
// the measured-optimal concurrency product. idx/vals via __ldg, bias folded
// into the accumulator init, plain vectorized store.
//
// Establshed floor model: 32MB compulsory random-256B gather traffic at
// ~45-50% HBM3e random-granule efficiency == ~8.3us. Ten structural
// variants (LDG scalar/wide/batched, evict hints, LDGSTS, TMA bulk,
// dual-path, 2-rows/warp, pipelined halves, streaming policies) all
// plateau at or above this; concurrency/path/policy levers are exhausted.

#define BATCH 4096
#define NNZ   32
#define DIM   64

__global__ void __launch_bounds__(256, 1) sparse_embedding_kernel(
    const int*   __restrict__ idx,
    const float* __restrict__ vals,
    const float* __restrict__ table,
    const float* __restrict__ bias,
    float*       __restrict__ out)
{
    const int gwarp = (blockIdx.x * blockDim.x + threadIdx.x) >> 5;
    const int lane  = threadIdx.x & 31;

    // Each lane holds one (idx, val) pair for this row; broadcast via shfl.
    const int   my_idx = __ldg(idx  + gwarp * NNZ + lane);
    const float my_val = __ldg(vals + gwarp * NNZ + lane);

    // Phase 1: issue ALL 32 gather loads before any consumer (MLP=32/warp).
    // .cg -> L2-direct, no L1 lookup (zero cross-warp reuse).
    float2 kv[NNZ];
#pragma unroll
    for (int n = 0; n < NNZ; ++n) {
        const int id = __shfl_sync(0xffffffffu, my_idx, n);
        kv[n] = __ldcg(reinterpret_cast<const float2*>(
            table + (size_t)id * DIM) + lane);
    }

    // Phase 2: accumulate (bias folded into init).
    float2 acc = __ldg(reinterpret_cast<const float2*>(bias) + lane);
#pragma unroll
    for (int n = 0; n < NNZ; ++n) {
        const float v = __shfl_sync(0xffffffffu, my_val, n);
        acc.x = fmaf(v, kv[n].x, acc.x);
        acc.y = fmaf(v, kv[n].y, acc.y);
    }

    reinterpret_cast<float2*>(out + (size_t)gwarp * DIM)[lane] = acc;
}

extern "C" void kernel_launch(void* const* d_in, const int* in_sizes, int n_in,
                              void* d_out, int out_size)
{
    const int*   idx   = (const int*)  d_in[0];
    const float* vals  = (const float*)d_in[1];
    const float* table = (const float*)d_in[2];
    const float* bias  = (const float*)d_in[3];
    float*       out   = (float*)d_out;

    // 4096 warps, 8 warps per 256-thread CTA -> 512 CTAs (R8 config).
    const int threads = 256;
    const int blocks  = (BATCH * 32) / threads;
    sparse_embedding_kernel<<<blocks, threads>>>(idx, vals, table, bias, out);
}

// round 15
// speedup vs baseline: 1.0037x; 1.0037x over previous
#include <cuda_runtime.h>

// SparseEmbedding: out[b, :] = sum_n vals[b,n] * kernel[idx[b,n], :] + bias
// BATCH=4096, NNZ=32, VOCAB=1e6, DIM=64. float32 everywhere, idx int32.
//
// R14: persistent grid-stride variant of the best config (R8). 512 work
// groups at 3 CTAs/SM means 444 resident + a 68-CTA SECOND WAVE that pays a
// launch + full gather round-trip on a mostly-idle machine. Instead launch
// exactly 444 CTAs (3 x 148 SMs) and grid-stride: the extra 68 row-groups
// run as a second loop iteration inside live CTAs, overlapping everyone
// else's work. Per-warp structure unchanged: all 32 gathers front-batched
// into registers via __ldcg (MLP=32), bias folded, vectorized store.

#define BATCH 4096
#define NNZ   32
#define DIM   64
#define NUM_SMS 148
#define CTAS (NUM_SMS * 3)          // 444: one full resident wave
#define WARPS_PER_CTA 8

__global__ void __launch_bounds__(256, 1) sparse_embedding_kernel(
    const int*   __restrict__ idx,
    const float* __restrict__ vals,
    const float* __restrict__ table,
    const float* __restrict__ bias,
    float*       __restrict__ out)
{
    const int lane  = threadIdx.x & 31;
    const int warp0 = blockIdx.x * WARPS_PER_CTA + (threadIdx.x >> 5);
    const int wstep = CTAS * WARPS_PER_CTA;       // 3552 warps in flight

    const float2 b = __ldg(reinterpret_cast<const float2*>(bias) + lane);

    for (int row = warp0; row < BATCH; row += wstep) {
        // Each lane holds one (idx, val) pair for this row; broadcast via shfl.
        const int   my_idx = __ldg(idx  + row * NNZ + lane);
        const float my_val = __ldg(vals + row * NNZ + lane);

        // Phase 1: issue ALL 32 gather loads before any consumer.
        float2 kv[NNZ];
#pragma unroll
        for (int n = 0; n < NNZ; ++n) {
            const int id = __shfl_sync(0xffffffffu, my_idx, n);
            kv[n] = __ldcg(reinterpret_cast<const float2*>(
                table + (size_t)id * DIM) + lane);
        }

        // Phase 2: accumulate (bias folded into init).
        float2 acc = b;
#pragma unroll
        for (int n = 0; n < NNZ; ++n) {
            const float v = __shfl_sync(0xffffffffu, my_val, n);
            acc.x = fmaf(v, kv[n].x, acc.x);
            acc.y = fmaf(v, kv[n].y, acc.y);
        }

        reinterpret_cast<float2*>(out + (size_t)row * DIM)[lane] = acc;
    }
}

extern "C" void kernel_launch(void* const* d_in, const int* in_sizes, int n_in,
                              void* d_out, int out_size)
{
    const int*   idx   = (const int*)  d_in[0];
    const float* vals  = (const float*)d_in[1];
    const float* table = (const float*)d_in[2];
    const float* bias  = (const float*)d_in[3];
    float*       out   = (float*)d_out;

    sparse_embedding_kernel<<<CTAS, WARPS_PER_CTA * 32>>>(
        idx, vals, table, bias, out);
}

// round 16
// speedup vs baseline: 1.0303x; 1.0265x over previous
#include <cuda_runtime.h>

// SparseEmbedding: out[b, :] = sum_n vals[b,n] * kernel[idx[b,n], :] + bias
// BATCH=4096, NNZ=32, VOCAB=1e6, DIM=64. float32 everywhere, idx int32.
//
// FINAL (R8 config; best measured 8.32us, noise band +-0.4us):
//   - one warp per batch row; lane l owns output dims [2l, 2l+1]
//   - idx/vals loaded once per lane, broadcast via shfl
//   - ALL 32 row-gathers front-batched into registers via __ldcg
//     (L2-direct, MLP=32/warp) before any FMA consumer
//   - 256-thread CTAs, regs=80 -> 3 CTAs/SM, 24 warps/SM: the measured
//     optimum of the (warps/SM x per-warp MLP) concurrency product
//   - bias folded into accumulator init; vectorized float2 store
//
// Floor analysis: 131072 random 256B gathers = 33.5MB compulsory traffic.
// At HBM3e random-granule efficiency (~50-65%) that is 6-7.5us of transfer
// plus ~1.3us dependency ramp (idx round-trip -> gather fill) == measured
// 8.3-8.7us plateau. Verified insensitive to: request path (LDG/L1,
// LDG.cg, LDG.256+evict_last, cp.async, TMA bulk, LDG+TMA dual),
// cache policy (evict_first/last, streaming), occupancy/MLP shape
// (16/32/64 per warp; 8-32 warps/SM), and wave structure (512 CTAs vs
// persistent 444). This is the pattern's hardware floor on this part.

#define BATCH 4096
#define NNZ   32
#define DIM   64

__global__ void __launch_bounds__(256, 1) sparse_embedding_kernel(
    const int*   __restrict__ idx,
    const float* __restrict__ vals,
    const float* __restrict__ table,
    const float* __restrict__ bias,
    float*       __restrict__ out)
{
    const int gwarp = (blockIdx.x * blockDim.x + threadIdx.x) >> 5;
    const int lane  = threadIdx.x & 31;

    // Each lane holds one (idx, val) pair for this row; broadcast via shfl.
    const int   my_idx = __ldg(idx  + gwarp * NNZ + lane);
    const float my_val = __ldg(vals + gwarp * NNZ + lane);

    // Phase 1: issue ALL 32 gather loads before any consumer (MLP=32/warp).
    // .cg -> L2-direct, no L1 lookup (zero cross-warp reuse).
    float2 kv[NNZ];
#pragma unroll
    for (int n = 0; n < NNZ; ++n) {
        const int id = __shfl_sync(0xffffffffu, my_idx, n);
        kv[n] = __ldcg(reinterpret_cast<const float2*>(
            table + (size_t)id * DIM) + lane);
    }

    // Phase 2: accumulate (bias folded into init).
    float2 acc = __ldg(reinterpret_cast<const float2*>(bias) + lane);
#pragma unroll
    for (int n = 0; n < NNZ; ++n) {
        const float v = __shfl_sync(0xffffffffu, my_val, n);
        acc.x = fmaf(v, kv[n].x, acc.x);
        acc.y = fmaf(v, kv[n].y, acc.y);
    }

    reinterpret_cast<float2*>(out + (size_t)gwarp * DIM)[lane] = acc;
}

extern "C" void kernel_launch(void* const* d_in, const int* in_sizes, int n_in,
                              void* d_out, int out_size)
{
    const int*   idx   = (const int*)  d_in[0];
    const float* vals  = (const float*)d_in[1];
    const float* table = (const float*)d_in[2];
    const float* bias  = (const float*)d_in[3];
    float*       out   = (float*)d_out;

    // 4096 warps, 8 warps per 256-thread CTA -> 512 CTAs.
    const int threads = 256;
    const int blocks  = (BATCH * 32) / threads;
    sparse_embedding_kernel<<<blocks, threads>>>(idx, vals, table, bias, out);
}